// round 1
// baseline (speedup 1.0000x reference)
#include <cuda_runtime.h>
#include <cuda_bf16.h>

// Output layout (flattened jax pytree, each region N*16 f32):
//   region 0: self_diff + interact_diff = -x + tanh(agg)
//   region 1: state_input (copy of x)
//   region 2: self_diff = -x
//   region 3: aggregated_sum (agg)  <- accumulated in-place via red.v4
//   region 4: interact_diff = tanh(agg)

__global__ void init_kernel(const float4* __restrict__ x,
                            float4* __restrict__ out, int n4) {
    int i = blockIdx.x * blockDim.x + threadIdx.x;
    if (i >= n4) return;
    float4 v = x[i];
    out[n4 + i] = v;                                            // region 1: x
    out[2 * n4 + i] = make_float4(-v.x, -v.y, -v.z, -v.w);      // region 2: -x
    out[3 * n4 + i] = make_float4(0.f, 0.f, 0.f, 0.f);          // region 3: zero agg
}

__global__ void edge_kernel(const float4* __restrict__ x,
                            const int* __restrict__ row,
                            const int* __restrict__ col,
                            const float* __restrict__ w,
                            float4* __restrict__ agg, int E) {
    int t = blockIdx.x * blockDim.x + threadIdx.x;
    int e = t >> 2;
    if (e >= E) return;
    int c = t & 3;

    int r  = __ldg(&row[e]);
    int cc = __ldg(&col[e]);
    float we = __ldg(&w[e]);

    float4 xr = __ldg(&x[r * 4 + c]);
    float4 xc = __ldg(&x[cc * 4 + c]);

    float4 v;
    v.x = we * __sinf(xr.x - xc.x);
    v.y = we * __sinf(xr.y - xc.y);
    v.z = we * __sinf(xr.z - xc.z);
    v.w = we * __sinf(xr.w - xc.w);

    float4* dst = agg + (cc * 4 + c);
    asm volatile("red.global.add.v4.f32 [%0], {%1, %2, %3, %4};"
                 :: "l"(dst), "f"(v.x), "f"(v.y), "f"(v.z), "f"(v.w)
                 : "memory");
}

__global__ void final_kernel(const float4* __restrict__ x,
                             float4* __restrict__ out, int n4) {
    int i = blockIdx.x * blockDim.x + threadIdx.x;
    if (i >= n4) return;
    float4 a = out[3 * n4 + i];           // agg (L2-resident after edge kernel)
    float4 t;
    t.x = tanhf(a.x); t.y = tanhf(a.y); t.z = tanhf(a.z); t.w = tanhf(a.w);
    out[4 * n4 + i] = t;                  // region 4: tanh(agg)
    float4 v = x[i];
    out[i] = make_float4(t.x - v.x, t.y - v.y, t.z - v.z, t.w - v.w); // region 0
}

extern "C" void kernel_launch(void* const* d_in, const int* in_sizes, int n_in,
                              void* d_out, int out_size) {
    const float4* x   = (const float4*)d_in[0];
    const int*    row = (const int*)d_in[1];
    const int*    col = (const int*)d_in[2];
    const float*  w   = (const float*)d_in[3];

    int N  = in_sizes[0] / 16;   // 100000
    int E  = in_sizes[1];        // 3200000
    int n4 = N * 4;              // float4s per region

    float4* out = (float4*)d_out;

    init_kernel<<<(n4 + 255) / 256, 256>>>(x, out, n4);
    edge_kernel<<<(4 * E + 255) / 256, 256>>>(x, row, col, w,
                                              out + (size_t)3 * n4, E);
    final_kernel<<<(n4 + 255) / 256, 256>>>(x, out, n4);
}

// round 2
// speedup vs baseline: 1.0291x; 1.0291x over previous
#include <cuda_runtime.h>
#include <cuda_bf16.h>

// Output layout (flattened jax pytree, each region N*16 f32 = n4 float4s):
//   region 0: -x + tanh(agg)
//   region 1: x (copy)
//   region 2: -x
//   region 3: agg   <- zeroed by memset, accumulated via red.global.add.v4
//   region 4: tanh(agg)

// Fused kernel: first `edgeBlocks` blocks do the L2-bound edge scatter;
// trailing blocks do the independent region-1/2 DRAM copies (overlaps).
__global__ void edge_copy_kernel(const float4* __restrict__ x,
                                 const int* __restrict__ row,
                                 const int* __restrict__ col,
                                 const float* __restrict__ w,
                                 float4* __restrict__ out,
                                 int n4, int E, int edgeBlocks) {
    if (blockIdx.x >= edgeBlocks) {
        // copy region: out[n4+i] = x[i], out[2n4+i] = -x[i]
        int i = (blockIdx.x - edgeBlocks) * blockDim.x + threadIdx.x;
        if (i < n4) {
            float4 v = __ldg(&x[i]);
            out[n4 + i] = v;
            out[2 * n4 + i] = make_float4(-v.x, -v.y, -v.z, -v.w);
        }
        return;
    }

    int t = blockIdx.x * blockDim.x + threadIdx.x;
    int e = t >> 2;
    if (e >= E) return;
    int c = t & 3;

    int r   = __ldg(&row[e]);
    int cc  = __ldg(&col[e]);
    float we = __ldg(&w[e]);

    float4 xr = __ldg(&x[r * 4 + c]);
    float4 xc = __ldg(&x[cc * 4 + c]);

    float4 v;
    v.x = we * __sinf(xr.x - xc.x);
    v.y = we * __sinf(xr.y - xc.y);
    v.z = we * __sinf(xr.z - xc.z);
    v.w = we * __sinf(xr.w - xc.w);

    float4* dst = out + (size_t)3 * n4 + (cc * 4 + c);
    asm volatile("red.global.add.v4.f32 [%0], {%1, %2, %3, %4};"
                 :: "l"(dst), "f"(v.x), "f"(v.y), "f"(v.z), "f"(v.w)
                 : "memory");
}

__global__ void final_kernel(const float4* __restrict__ x,
                             float4* __restrict__ out, int n4) {
    int i = blockIdx.x * blockDim.x + threadIdx.x;
    if (i >= n4) return;
    float4 a = out[3 * n4 + i];   // agg (L2-resident right after edge kernel)
    float4 v = __ldg(&x[i]);      // issue early; independent
    float4 t;
    t.x = tanhf(a.x); t.y = tanhf(a.y); t.z = tanhf(a.z); t.w = tanhf(a.w);
    out[4 * n4 + i] = t;                                                  // region 4
    out[i] = make_float4(t.x - v.x, t.y - v.y, t.z - v.z, t.w - v.w);     // region 0
}

extern "C" void kernel_launch(void* const* d_in, const int* in_sizes, int n_in,
                              void* d_out, int out_size) {
    const float4* x   = (const float4*)d_in[0];
    const int*    row = (const int*)d_in[1];
    const int*    col = (const int*)d_in[2];
    const float*  w   = (const float*)d_in[3];

    int N  = in_sizes[0] / 16;   // 100000
    int E  = in_sizes[1];        // 3200000
    int n4 = N * 4;

    float4* out = (float4*)d_out;

    // Zero agg region (graph-capturable memset node).
    cudaMemsetAsync(out + (size_t)3 * n4, 0, (size_t)n4 * sizeof(float4));

    int edgeBlocks = (4 * E + 255) / 256;          // 50000
    int copyBlocks = (n4 + 255) / 256;             // 1563
    edge_copy_kernel<<<edgeBlocks + copyBlocks, 256>>>(x, row, col, w,
                                                       out, n4, E, edgeBlocks);

    final_kernel<<<(n4 + 255) / 256, 256>>>(x, out, n4);
}